// round 16
// baseline (speedup 1.0000x reference)
#include <cuda_runtime.h>
#include <cfloat>

#define BATCH 4
#define NREF  8192
#define MQ    8192
#define KNN   16
#define WARPS_PER_BLOCK 8
#define NPAIRS (BATCH * NREF / 2)

// SoA packed candidate scratch: entry i = batch b, tile j, lane l holds
// candidates n_lo = b*NREF + j*64 + l  (low 32 bits / elem0)
//        and n_hi = n_lo + 32          (high 32 bits / elem1).
__device__ unsigned long long gX[NPAIRS], gY[NPAIRS], gZ[NPAIRS], gW[NPAIRS];

typedef unsigned long long u64;

// Sum of squares, form h2s (bit-matches reference):
__device__ __forceinline__ float sumsq_h2s(float x, float y, float z) {
    return __fadd_rn(__fmaf_rn(x, x, __fmul_rn(z, z)), __fmul_rn(y, y));
}

__device__ __forceinline__ u64 pack2(float lo, float hi) {
    return ((u64)__float_as_uint(hi) << 32) | (u64)__float_as_uint(lo);
}
__device__ __forceinline__ u64 mul2(u64 a, u64 b) {
    u64 r; asm("mul.rn.f32x2 %0, %1, %2;" : "=l"(r) : "l"(a), "l"(b)); return r;
}
__device__ __forceinline__ u64 add2(u64 a, u64 b) {
    u64 r; asm("add.rn.f32x2 %0, %1, %2;" : "=l"(r) : "l"(a), "l"(b)); return r;
}
__device__ __forceinline__ u64 fma2(u64 a, u64 b, u64 c) {
    u64 r; asm("fma.rn.f32x2 %0, %1, %2, %3;" : "=l"(r) : "l"(a), "l"(b), "l"(c)); return r;
}
__device__ __forceinline__ float lo32(u64 v) { return __uint_as_float((unsigned)v); }
__device__ __forceinline__ float hi32(u64 v) { return __uint_as_float((unsigned)(v >> 32)); }

// ---------------------------------------------------------------------------
// Pack kernel: SoA pair layout + per-point |r|^2 (h2s rounding).
// ---------------------------------------------------------------------------
__global__ void knn_pack_kernel(const float* __restrict__ ref) {
    int i = blockIdx.x * blockDim.x + threadIdx.x;
    if (i >= NPAIRS) return;
    int b  = i / (NREF / 2);
    int li = i % (NREF / 2);
    int n_lo = b * NREF + ((li >> 5) << 6) + (li & 31);
    int n_hi = n_lo + 32;
    float x0 = ref[n_lo*3], y0 = ref[n_lo*3+1], z0 = ref[n_lo*3+2];
    float x1 = ref[n_hi*3], y1 = ref[n_hi*3+1], z1 = ref[n_hi*3+2];
    gX[i] = pack2(x0, x1);
    gY[i] = pack2(y0, y1);
    gZ[i] = pack2(z0, z1);
    gW[i] = pack2(sumsq_h2s(x0, y0, z0), sumsq_h2s(x1, y1, z1));
}

// ---------------------------------------------------------------------------
// Main kernel: TWO queries per warp, 64 candidates/iter, f32x2 packed eval.
// Lanes 0..15 hold query A's sorted top-16; lanes 16..31 hold query B's.
// Rounding (bit-exact vs reference, f32x2 == per-element scalar RN):
//   cross = fma(q2,rz, fma(q1,ry, rn(q0*rx)))
//   sq    = rn( fma(x,x, rn(z*z)) + rn(y*y) )
//   raw   = fma(-2, cross, rn(qsq+rsq))   [== rn((qsq+rsq)-2*cross)]
// Filter on raw; clamp at insert; rank-16 inserts are structural no-ops.
// Mask-lo (candidates base..base+31) processed before mask-hi: ascending
// index order => lax.top_k tie stability preserved.
// ---------------------------------------------------------------------------
__global__ void __launch_bounds__(WARPS_PER_BLOCK * 32)
knn_topk_kernel(const float* __restrict__ query,
                float* __restrict__ out_dist,
                float* __restrict__ out_idx) {
    const unsigned FULL = 0xFFFFFFFFu;
    const int warp = threadIdx.x >> 5;
    const int lane = threadIdx.x & 31;
    const int pair = blockIdx.x * WARPS_PER_BLOCK + warp;
    const int half = lane >> 4;
    const int hl   = lane & 15;
    const int gmy  = (pair << 1) + half;
    const int b    = gmy >> 13;

    const float mq0 = __ldg(&query[gmy * 3 + 0]);
    const float mq1 = __ldg(&query[gmy * 3 + 1]);
    const float mq2 = __ldg(&query[gmy * 3 + 2]);
    const float msq = sumsq_h2s(mq0, mq1, mq2);

    // Broadcast both queries, pack each coord as [q,q] for f32x2 chains.
    const u64 QA0 = pack2(__shfl_sync(FULL, mq0, 0),  __shfl_sync(FULL, mq0, 0));
    const u64 QA1 = pack2(__shfl_sync(FULL, mq1, 0),  __shfl_sync(FULL, mq1, 0));
    const u64 QA2 = pack2(__shfl_sync(FULL, mq2, 0),  __shfl_sync(FULL, mq2, 0));
    const u64 QAS = pack2(__shfl_sync(FULL, msq, 0),  __shfl_sync(FULL, msq, 0));
    const u64 QB0 = pack2(__shfl_sync(FULL, mq0, 16), __shfl_sync(FULL, mq0, 16));
    const u64 QB1 = pack2(__shfl_sync(FULL, mq1, 16), __shfl_sync(FULL, mq1, 16));
    const u64 QB2 = pack2(__shfl_sync(FULL, mq2, 16), __shfl_sync(FULL, mq2, 16));
    const u64 QBS = pack2(__shfl_sync(FULL, msq, 16), __shfl_sync(FULL, msq, 16));
    const u64 M2  = pack2(-2.0f, -2.0f);

    float slotD = FLT_MAX;
    int   slotI = 0x7FFFFFFF;
    float kthA = FLT_MAX;
    float kthB = FLT_MAX;

    #define INSERT_LOOP(bm, raw, base, h)                                     \
        while (bm) {                                                          \
            const int s = __ffs(bm) - 1;                                      \
            bm &= bm - 1;                                                     \
            const float nd = fmaxf(__shfl_sync(FULL, raw, s), 0.0f);          \
            const int ni = (base) + s;                                        \
            const unsigned le =                                               \
                __ballot_sync(FULL, (half == (h)) && (slotD <= nd));          \
            const int pos = __popc(le);                                       \
            const float upD = __shfl_up_sync(FULL, slotD, 1);                 \
            const int   upI = __shfl_up_sync(FULL, slotI, 1);                 \
            if (half == (h)) {                                                \
                if (hl == pos)      { slotD = nd;  slotI = ni;  }             \
                else if (hl > pos)  { slotD = upD; slotI = upI; }             \
            }                                                                 \
        }

    const int tilebase = (b * (NREF / 2)) + lane;
    #pragma unroll 2
    for (int j = 0; j < NREF / 64; ++j) {
        const int idx = tilebase + (j << 5);
        const u64 RX = __ldg(&gX[idx]);
        const u64 RY = __ldg(&gY[idx]);
        const u64 RZ = __ldg(&gZ[idx]);
        const u64 RW = __ldg(&gW[idx]);

        // Query A: cross chain + raw d2, two candidates per instruction
        u64 CA = mul2(QA0, RX);
        CA = fma2(QA1, RY, CA);
        CA = fma2(QA2, RZ, CA);
        const u64 RA = fma2(M2, CA, add2(QAS, RW));
        // Query B
        u64 CB = mul2(QB0, RX);
        CB = fma2(QB1, RY, CB);
        CB = fma2(QB2, RZ, CB);
        const u64 RB = fma2(M2, CB, add2(QBS, RW));

        const float rA0 = lo32(RA), rA1 = hi32(RA);
        const float rB0 = lo32(RB), rB1 = hi32(RB);

        unsigned mA0 = __ballot_sync(FULL, rA0 < kthA);
        unsigned mA1 = __ballot_sync(FULL, rA1 < kthA);
        unsigned mB0 = __ballot_sync(FULL, rB0 < kthB);
        unsigned mB1 = __ballot_sync(FULL, rB1 < kthB);

        const int base = j << 6;
        if (mA0 | mA1) {
            INSERT_LOOP(mA0, rA0, base, 0)
            INSERT_LOOP(mA1, rA1, base + 32, 0)
            kthA = __shfl_sync(FULL, slotD, 15);
        }
        if (mB0 | mB1) {
            INSERT_LOOP(mB0, rB0, base, 1)
            INSERT_LOOP(mB1, rB1, base + 32, 1)
            kthB = __shfl_sync(FULL, slotD, 31);
        }
    }
    #undef INSERT_LOOP

    out_dist[gmy * KNN + hl] = __fsqrt_rn(slotD);
    out_idx [gmy * KNN + hl] = (float)slotI;
}

// ---------------------------------------------------------------------------
// kernel_launch: inputs per metadata order: ref [B,N,3] f32, query [B,M,3] f32,
// k (ignored; compile-time 16). Output: dist [B,M,16] f32 then idx [B,M,16].
// ---------------------------------------------------------------------------
extern "C" void kernel_launch(void* const* d_in, const int* in_sizes, int n_in,
                              void* d_out, int out_size) {
    const float* ref   = (const float*)d_in[0];
    const float* query = (const float*)d_in[1];
    float* out = (float*)d_out;

    knn_pack_kernel<<<(NPAIRS + 255) / 256, 256>>>(ref);

    const int nq = BATCH * MQ;                     // 32768 queries
    const int npairs = nq / 2;                     // 16384 warps
    knn_topk_kernel<<<npairs / WARPS_PER_BLOCK, WARPS_PER_BLOCK * 32>>>(
        query, out, out + (size_t)nq * KNN);
}

// round 17
// speedup vs baseline: 1.1069x; 1.1069x over previous
#include <cuda_runtime.h>
#include <cfloat>

#define BATCH 4
#define NREF  8192
#define MQ    8192
#define KNN   16
#define WARPS_PER_BLOCK 8

// Packed ref points: x, y, z, |r|^2   (512 KB static scratch — allocation-free)
__device__ float4 g_packed[BATCH * NREF];

// Sum of squares, form h2s (bit-matches reference):
//   rn( fma(x,x, rn(z*z)) + rn(y*y) )
__device__ __forceinline__ float sumsq_h2s(float x, float y, float z) {
    return __fadd_rn(__fmaf_rn(x, x, __fmul_rn(z, z)), __fmul_rn(y, y));
}

__global__ void knn_pack_kernel(const float* __restrict__ ref) {
    int i = blockIdx.x * blockDim.x + threadIdx.x;
    if (i >= BATCH * NREF) return;
    float x = ref[i * 3 + 0];
    float y = ref[i * 3 + 1];
    float z = ref[i * 3 + 2];
    g_packed[i] = make_float4(x, y, z, sumsq_h2s(x, y, z));
}

// raw d2 (unclamped): fma(-2, cross, rn(qsq+rsq)) — bitwise equal to
// rn((qsq+rsq) - 2*cross) since 2*cross is exact.
__device__ __forceinline__ float rawd2(float q0, float q1, float q2,
                                       float qsq, const float4& r) {
    const float cr = __fmaf_rn(q2, r.z, __fmaf_rn(q1, r.y, __fmul_rn(q0, r.x)));
    return __fmaf_rn(-2.0f, cr, __fadd_rn(qsq, r.w));
}

// ---------------------------------------------------------------------------
// Main kernel: FOUR queries per warp, 64 candidates per iteration.
//   slot set 0: lanes 0..15 = query A (quad*4+0), lanes 16..31 = B (quad*4+1)
//   slot set 1: lanes 0..15 = query C (quad*4+2), lanes 16..31 = D (quad*4+3)
// Each iteration loads 64 candidates once (2x LDG.128), evaluates 4 queries.
// Filter on raw (unclamped) d2; clamp at insert; rank-16 inserts are no-ops.
// Scan order ascending everywhere => lax.top_k tie stability preserved.
// ---------------------------------------------------------------------------
__global__ void __launch_bounds__(WARPS_PER_BLOCK * 32)
knn_topk_kernel(const float* __restrict__ query,
                float* __restrict__ out_dist,
                float* __restrict__ out_idx) {
    const unsigned FULL = 0xFFFFFFFFu;
    const int warp = threadIdx.x >> 5;
    const int lane = threadIdx.x & 31;
    const int quad = blockIdx.x * WARPS_PER_BLOCK + warp;   // 8192 quads
    const int half = lane >> 4;
    const int hl   = lane & 15;
    const int q0i  = quad << 2;          // first of 4 consecutive queries
    const int b    = q0i >> 13;          // all 4 in same batch (4 | 8192)

    const float4* __restrict__ pref = &g_packed[b * NREF];

    // Uniform broadcast loads of the 4 queries' coords (L1-cached).
    const float a0 = __ldg(&query[(q0i + 0) * 3 + 0]);
    const float a1 = __ldg(&query[(q0i + 0) * 3 + 1]);
    const float a2 = __ldg(&query[(q0i + 0) * 3 + 2]);
    const float b0 = __ldg(&query[(q0i + 1) * 3 + 0]);
    const float b1 = __ldg(&query[(q0i + 1) * 3 + 1]);
    const float b2 = __ldg(&query[(q0i + 1) * 3 + 2]);
    const float c0 = __ldg(&query[(q0i + 2) * 3 + 0]);
    const float c1 = __ldg(&query[(q0i + 2) * 3 + 1]);
    const float c2 = __ldg(&query[(q0i + 2) * 3 + 2]);
    const float e0 = __ldg(&query[(q0i + 3) * 3 + 0]);
    const float e1 = __ldg(&query[(q0i + 3) * 3 + 1]);
    const float e2 = __ldg(&query[(q0i + 3) * 3 + 2]);
    const float asq = sumsq_h2s(a0, a1, a2);
    const float bsq = sumsq_h2s(b0, b1, b2);
    const float csq = sumsq_h2s(c0, c1, c2);
    const float esq = sumsq_h2s(e0, e1, e2);

    // Two slot sets (sorted per half). FLT_MAX sentinels.
    float sD0 = FLT_MAX, sD1 = FLT_MAX;
    int   sI0 = 0x7FFFFFFF, sI1 = 0x7FFFFFFF;
    float kthA = FLT_MAX, kthB = FLT_MAX, kthC = FLT_MAX, kthD = FLT_MAX;

    #define INSERT_LOOP(bm, raw, base, h, SD, SI)                             \
        while (bm) {                                                          \
            const int s = __ffs(bm) - 1;                                      \
            bm &= bm - 1;                                                     \
            const float nd = fmaxf(__shfl_sync(FULL, raw, s), 0.0f);          \
            const int ni = (base) + s;                                        \
            const unsigned le =                                               \
                __ballot_sync(FULL, (half == (h)) && (SD <= nd));             \
            const int pos = __popc(le);                                       \
            const float upD = __shfl_up_sync(FULL, SD, 1);                    \
            const int   upI = __shfl_up_sync(FULL, SI, 1);                    \
            if (half == (h)) {                                                \
                if (hl == pos)      { SD = nd;  SI = ni;  }                   \
                else if (hl > pos)  { SD = upD; SI = upI; }                   \
            }                                                                 \
        }

    const float4* p = pref + lane;
    for (int j = 0; j < NREF / 64; ++j, p += 64) {
        const int base = j << 6;
        const float4 r0 = __ldg(p);
        const float4 r1 = __ldg(p + 32);

        const float rA0 = rawd2(a0, a1, a2, asq, r0);
        const float rA1 = rawd2(a0, a1, a2, asq, r1);
        const float rB0 = rawd2(b0, b1, b2, bsq, r0);
        const float rB1 = rawd2(b0, b1, b2, bsq, r1);
        const float rC0 = rawd2(c0, c1, c2, csq, r0);
        const float rC1 = rawd2(c0, c1, c2, csq, r1);
        const float rD0 = rawd2(e0, e1, e2, esq, r0);
        const float rD1 = rawd2(e0, e1, e2, esq, r1);

        unsigned mA0 = __ballot_sync(FULL, rA0 < kthA);
        unsigned mA1 = __ballot_sync(FULL, rA1 < kthA);
        unsigned mB0 = __ballot_sync(FULL, rB0 < kthB);
        unsigned mB1 = __ballot_sync(FULL, rB1 < kthB);
        unsigned mC0 = __ballot_sync(FULL, rC0 < kthC);
        unsigned mC1 = __ballot_sync(FULL, rC1 < kthC);
        unsigned mD0 = __ballot_sync(FULL, rD0 < kthD);
        unsigned mD1 = __ballot_sync(FULL, rD1 < kthD);

        if (mA0 | mA1) {
            INSERT_LOOP(mA0, rA0, base, 0, sD0, sI0)
            INSERT_LOOP(mA1, rA1, base + 32, 0, sD0, sI0)
            kthA = __shfl_sync(FULL, sD0, 15);
        }
        if (mB0 | mB1) {
            INSERT_LOOP(mB0, rB0, base, 1, sD0, sI0)
            INSERT_LOOP(mB1, rB1, base + 32, 1, sD0, sI0)
            kthB = __shfl_sync(FULL, sD0, 31);
        }
        if (mC0 | mC1) {
            INSERT_LOOP(mC0, rC0, base, 0, sD1, sI1)
            INSERT_LOOP(mC1, rC1, base + 32, 0, sD1, sI1)
            kthC = __shfl_sync(FULL, sD1, 15);
        }
        if (mD0 | mD1) {
            INSERT_LOOP(mD0, rD0, base, 1, sD1, sI1)
            INSERT_LOOP(mD1, rD1, base + 32, 1, sD1, sI1)
            kthD = __shfl_sync(FULL, sD1, 31);
        }
    }
    #undef INSERT_LOOP

    // set0: queries q0i+half ; set1: queries q0i+2+half
    const int g0 = q0i + half;
    const int g1 = q0i + 2 + half;
    out_dist[g0 * KNN + hl] = __fsqrt_rn(sD0);
    out_idx [g0 * KNN + hl] = (float)sI0;
    out_dist[g1 * KNN + hl] = __fsqrt_rn(sD1);
    out_idx [g1 * KNN + hl] = (float)sI1;
}

// ---------------------------------------------------------------------------
// kernel_launch: inputs per metadata order: ref [B,N,3] f32, query [B,M,3] f32,
// k (ignored; compile-time 16). Output: dist [B,M,16] f32 then idx [B,M,16].
// ---------------------------------------------------------------------------
extern "C" void kernel_launch(void* const* d_in, const int* in_sizes, int n_in,
                              void* d_out, int out_size) {
    const float* ref   = (const float*)d_in[0];
    const float* query = (const float*)d_in[1];
    float* out = (float*)d_out;

    knn_pack_kernel<<<(BATCH * NREF + 255) / 256, 256>>>(ref);

    const int nq = BATCH * MQ;                     // 32768 queries
    const int nquads = nq / 4;                     // 8192 warps
    knn_topk_kernel<<<nquads / WARPS_PER_BLOCK, WARPS_PER_BLOCK * 32>>>(
        query, out, out + (size_t)nq * KNN);
}